// round 11
// baseline (speedup 1.0000x reference)
#include <cuda_runtime.h>
#include <math.h>

// CNF_9663676416569: vector field + exact divergence via weight-precomputed E.
//
// dx  = tanh(tanh([t,x] @ W1 + b1) @ W2 + b2) @ W3 + b3
// div = sum_j (1-h2_j^2) * sum_m (1-h1_m^2) * E[m,j]
//   where E[m,j] = W2[m,j] * sum_k W1[1+k, m] * W3[j, k]   (weights only)
//
// R8: duplicate the A-operand (h1) in SMEM instead of the B-operands.
//     Col-packed FFMA2: A = direct LDS.128 of dup'd pairs, B = plain
//     LDG.128 of W2 / f32 E (non-dup -> LDG count & L2 bytes halved).
//     4 rows x 8 cols per thread, 256 thr, MT=32, 1 CTA/SM.

#define Hm 512
#define Dm 64
#define MT 32
#define H1P 68          // dup'd h1 pitch: 64 dup floats + 4 (272B, 16B-mult)
#define STP 36          // s_st pitch: 32 rows + 4

typedef unsigned long long ull;

#define SGN2  0x8000000080000000ULL
#define ONES2 0x3F8000003F800000ULL

__device__ float g_E[Hm * Hm];                  // f32, non-dup
__device__ __align__(16) ull g_W1d[65 * Hm];    // (w,w) pairs for Phase A
__device__ __align__(16) ull g_W3d[Hm * Dm];    // (w,w) pairs for DX

__device__ __forceinline__ ull pack2(float lo, float hi) {
    ull d; asm("mov.b64 %0, {%1, %2};" : "=l"(d) : "f"(lo), "f"(hi)); return d;
}
__device__ __forceinline__ void unpack2(ull v, float& lo, float& hi) {
    asm("mov.b64 {%0, %1}, %2;" : "=f"(lo), "=f"(hi) : "l"(v));
}
__device__ __forceinline__ void ffma2(ull& d, ull a, ull b) {
    asm("fma.rn.f32x2 %0, %1, %2, %0;" : "+l"(d) : "l"(a), "l"(b));
}
__device__ __forceinline__ ull ffma2o(ull a, ull b, ull c) {
    ull d;
    asm("fma.rn.f32x2 %0, %1, %2, %3;" : "=l"(d) : "l"(a), "l"(b), "l"(c));
    return d;
}
__device__ __forceinline__ void fadd2(ull& d, ull a) {
    asm("add.rn.f32x2 %0, %0, %1;" : "+l"(d) : "l"(a));
}

// ---------------------------------------------------------------------------
// Precompute: E = W2 .* (W1[1:,:]^T @ W3^T)  (f32);  dup W1 and W3.
// ---------------------------------------------------------------------------
__global__ __launch_bounds__(256)
void compute_E_kernel(const float* __restrict__ W1,
                      const float* __restrict__ W2,
                      const float* __restrict__ W3) {
    __shared__ float As[64][33];
    __shared__ float Bs[32][65];
    const int m0 = blockIdx.x * 32;
    const int j0 = blockIdx.y * 32;
    const int tid = threadIdx.x;

    for (int p = tid; p < 64 * 32; p += 256) {
        int i = p >> 5, ml = p & 31;
        As[i][ml] = W1[(1 + i) * Hm + m0 + ml];
    }
    for (int p = tid; p < 32 * 64; p += 256) {
        int i = p & 63, jl = p >> 6;
        Bs[jl][i] = W3[(j0 + jl) * 64 + i];
    }
    __syncthreads();

    const int jl = tid & 31;
    const int mg = tid >> 5;
    float acc[4] = {0.f, 0.f, 0.f, 0.f};
    #pragma unroll
    for (int i = 0; i < 64; i++) {
        float b = Bs[jl][i];
        #pragma unroll
        for (int q = 0; q < 4; q++)
            acc[q] = fmaf(As[i][mg * 4 + q], b, acc[q]);
    }
    #pragma unroll
    for (int q = 0; q < 4; q++) {
        int m = m0 + mg * 4 + q;
        int j = j0 + jl;
        g_E[m * Hm + j] = W2[m * Hm + j] * acc[q];
    }

    if (blockIdx.y == 0) {          // dup W1 columns m0..m0+31
        for (int p = tid; p < 65 * 32; p += 256) {
            int c = p >> 5, ml = p & 31;
            const float w = W1[c * Hm + m0 + ml];
            g_W1d[c * Hm + m0 + ml] = pack2(w, w);
        }
    } else if (blockIdx.y == 1) {   // dup W3 rows m0..m0+31
        for (int p = tid; p < 32 * 64; p += 256) {
            int r = p >> 6, cc = p & 63;
            const float w = W3[(m0 + r) * Dm + cc];
            g_W3d[(m0 + r) * Dm + cc] = pack2(w, w);
        }
    }
}

// ---------------------------------------------------------------------------
// Main kernel: one CTA = 32 batch rows, 256 threads, 1 CTA/SM.
// Phase B thread map: rp = tid&7 (rows 4*rp..+3), cg = tid>>3 (cols 8*cg..+7
// within a 256-col chunk; 2 chunks).
// SMEM: s_xaT[65][32], s_h1d[512][68] (k-major, values DUPLICATED),
//       s_st[256][36] (h2 transposed [col][row], non-dup), s_div[32]
// ---------------------------------------------------------------------------
__global__ __launch_bounds__(256, 1)
void cnf_main_kernel(const float* __restrict__ t,
                     const float* __restrict__ x,
                     const float* __restrict__ W1,
                     const float* __restrict__ b1,
                     const float* __restrict__ W2,
                     const float* __restrict__ b2,
                     const float* __restrict__ W3,
                     const float* __restrict__ b3,
                     float* __restrict__ out) {
    extern __shared__ float sm[];
    float* s_xaT = sm;                        // 65*32  = 2080
    float* s_h1d = sm + 65 * 32;              // 512*68 = 34816
    float* s_st  = s_h1d + 512 * H1P;         // 256*36 = 9216
    float* s_div = s_st + 256 * STP;          // 32

    const int tid  = threadIdx.x;
    const int row0 = blockIdx.x * MT;

    if (tid < MT) s_div[tid] = 0.f;

    // ---- load [t, x] tile transposed ----
    const float tval = t[0];
    for (int p = tid; p < 65 * 32; p += 256) {
        int c = p >> 5, r = p & 31;
        s_xaT[c * 32 + r] = (c == 0) ? tval
                                     : x[(size_t)(row0 + r) * 65 + (c - 1)];
    }
    __syncthreads();

    // ---- Phase A: H1 = tanh(Xa @ W1 + b1); 2 n per thread; DUP writes ----
    #pragma unroll
    for (int q = 0; q < 2; q++) {
        const int n = tid + q * 256;
        const float bb = b1[n];
        const ull pb = pack2(bb, bb);
        ull acc2[16];
        #pragma unroll
        for (int p = 0; p < 16; p++) acc2[p] = pb;
        #pragma unroll 4
        for (int c = 0; c < 65; c++) {
            const ull pw = g_W1d[c * Hm + n];
            const ull* xa = (const ull*)(s_xaT + c * 32);
            #pragma unroll
            for (int p = 0; p < 16; p++) ffma2(acc2[p], xa[p], pw);
        }
        float* dst = s_h1d + n * H1P;
        #pragma unroll
        for (int p = 0; p < 16; p++) {
            float lo, hi; unpack2(acc2[p], lo, hi);
            const float tl = tanhf(lo), th = tanhf(hi);
            *(float4*)(dst + 4 * p) = make_float4(tl, tl, th, th);
        }
    }
    __syncthreads();

    // ---- Phase B ----
    const int rp = tid & 7;
    const int cg = tid >> 3;          // 0..31
    const int r0 = rp * 4;            // 4 rows
    const int d0 = cg * 8;            // 8 chunk-local cols

    const int cgm = cg & 15;          // DX col group (two kk-half replicas)
    const int d3  = cgm * 4;          // 4 dx cols
    const int kk0 = (cg >> 4) * 128;  // DX kk half

    ull accDX[2][4];
    #pragma unroll
    for (int h = 0; h < 2; h++)
        #pragma unroll
        for (int j = 0; j < 4; j++) accDX[h][j] = 0ull;
    float divacc[4] = {0.f, 0.f, 0.f, 0.f};

    for (int ch = 0; ch < 2; ch++) {
        const int n0 = ch * 256;

        // init accZ with b2 pairs (non-dup direct loads)
        const float4* pb2p = (const float4*)(b2 + n0 + d0);
        const ulonglong2 bA = *(const ulonglong2*)(pb2p);
        const ulonglong2 bB = *(const ulonglong2*)(pb2p + 1);
        ull accZ[4][4], accU[4][4];
        #pragma unroll
        for (int i = 0; i < 4; i++) {
            accZ[i][0] = bA.x; accZ[i][1] = bA.y;
            accZ[i][2] = bB.x; accZ[i][3] = bB.y;
            accU[i][0] = 0ull; accU[i][1] = 0ull;
            accU[i][2] = 0ull; accU[i][3] = 0ull;
        }

        const float* __restrict__ ph = s_h1d + 8 * rp;
        const float* __restrict__ pWb = W2  + n0 + d0;
        const float* __restrict__ pEb = g_E + n0 + d0;

        #pragma unroll 4
        for (int k = 0; k < Hm; k++) {
            // A: dup'd pairs, rows 4rp..4rp+3
            const ulonglong2 a01 = *(const ulonglong2*)(ph + k * H1P);
            const ulonglong2 a23 = *(const ulonglong2*)(ph + k * H1P + 4);
            const ull av[4] = {a01.x, a01.y, a23.x, a23.y};
            ull gv[4];
            #pragma unroll
            for (int i = 0; i < 4; i++)
                gv[i] = ffma2o(av[i], av[i] ^ SGN2, ONES2);   // (1-h^2, 1-h^2)

            // B: non-dup LDG.128 (cols d0..d0+7 as 4 packed pairs)
            const ulonglong2 wA = *(const ulonglong2*)(pWb + (size_t)k * Hm);
            const ulonglong2 wB = *(const ulonglong2*)(pWb + (size_t)k * Hm + 4);
            const ulonglong2 eA = *(const ulonglong2*)(pEb + (size_t)k * Hm);
            const ulonglong2 eB = *(const ulonglong2*)(pEb + (size_t)k * Hm + 4);

            #pragma unroll
            for (int i = 0; i < 4; i++) {
                ffma2(accZ[i][0], av[i], wA.x);
                ffma2(accZ[i][1], av[i], wA.y);
                ffma2(accZ[i][2], av[i], wB.x);
                ffma2(accZ[i][3], av[i], wB.y);
                ffma2(accU[i][0], gv[i], eA.x);
                ffma2(accU[i][1], gv[i], eA.y);
                ffma2(accU[i][2], gv[i], eB.x);
                ffma2(accU[i][3], gv[i], eB.y);
            }
        }

        // h2 / g2 / div partials; stage h2 transposed [col][row]
        float h2v[8][4];                 // [chunk-local col j][row i]
        #pragma unroll
        for (int i = 0; i < 4; i++) {
            float dvi = 0.f;
            #pragma unroll
            for (int jp = 0; jp < 4; jp++) {
                float zl, zh, ul, uh;
                unpack2(accZ[i][jp], zl, zh);
                unpack2(accU[i][jp], ul, uh);
                const float hl = tanhf(zl), hh = tanhf(zh);
                dvi = fmaf(fmaf(-hl, hl, 1.f), ul, dvi);
                dvi = fmaf(fmaf(-hh, hh, 1.f), uh, dvi);
                h2v[2 * jp][i]     = hl;
                h2v[2 * jp + 1][i] = hh;
            }
            divacc[i] += dvi;
        }
        __syncthreads();   // protect s_st from previous DX read
        #pragma unroll
        for (int j = 0; j < 8; j++)
            *(float4*)(s_st + (d0 + j) * STP + r0) =
                make_float4(h2v[j][0], h2v[j][1], h2v[j][2], h2v[j][3]);
        __syncthreads();

        // accDX += h2_chunk[:, kk0:kk0+128] @ W3[n0+kk0 : n0+kk0+128, d3:d3+4]
        const ulonglong2* __restrict__ pW3 =
            (const ulonglong2*)g_W3d + (d3 >> 1);
        #pragma unroll 8
        for (int kk = 0; kk < 128; kk++) {
            const int kc = kk0 + kk;
            const ulonglong2 a = *(const ulonglong2*)(s_st + kc * STP + r0);
            const ulonglong2 w0 = pW3[(size_t)(n0 + kc) * 32];
            const ulonglong2 w1 = pW3[(size_t)(n0 + kc) * 32 + 1];
            ffma2(accDX[0][0], a.x, w0.x); ffma2(accDX[0][1], a.x, w0.y);
            ffma2(accDX[0][2], a.x, w1.x); ffma2(accDX[0][3], a.x, w1.y);
            ffma2(accDX[1][0], a.y, w0.x); ffma2(accDX[1][1], a.y, w0.y);
            ffma2(accDX[1][2], a.y, w1.x); ffma2(accDX[1][3], a.y, w1.y);
        }
        __syncthreads();
    }

    // ---- DX replica reduction (cg>=16 half adds into cg<16 half) ----
    ull* s_red = (ull*)s_st;
    if (cg >= 16) {
        ull* dst = s_red + ((size_t)(cgm * 8 + rp)) * 8;
        #pragma unroll
        for (int h = 0; h < 2; h++)
            #pragma unroll
            for (int j = 0; j < 4; j++) dst[h * 4 + j] = accDX[h][j];
    }
    __syncthreads();
    if (cg < 16) {
        const ull* src = s_red + ((size_t)(cgm * 8 + rp)) * 8;
        #pragma unroll
        for (int h = 0; h < 2; h++)
            #pragma unroll
            for (int j = 0; j < 4; j++) fadd2(accDX[h][j], src[h * 4 + j]);
    }

    // ---- epilogue ----
    #pragma unroll
    for (int i = 0; i < 4; i++) atomicAdd(&s_div[r0 + i], divacc[i]);

    if (cg < 16) {
        const float4 b3v = *(const float4*)(b3 + d3);
        #pragma unroll
        for (int h = 0; h < 2; h++) {
            float v[2][4];
            #pragma unroll
            for (int j = 0; j < 4; j++) unpack2(accDX[h][j], v[0][j], v[1][j]);
            #pragma unroll
            for (int s = 0; s < 2; s++) {
                const size_t ro = (size_t)(row0 + r0 + 2 * h + s) * 65 + d3;
                out[ro + 0] = v[s][0] + b3v.x;
                out[ro + 1] = v[s][1] + b3v.y;
                out[ro + 2] = v[s][2] + b3v.z;
                out[ro + 3] = v[s][3] + b3v.w;
            }
        }
    }
    __syncthreads();
    if (tid < MT)
        out[(size_t)(row0 + tid) * 65 + 64] = s_div[tid];
}

// ---------------------------------------------------------------------------
extern "C" void kernel_launch(void* const* d_in, const int* in_sizes, int n_in,
                              void* d_out, int out_size) {
    const float* t  = (const float*)d_in[0];
    const float* x  = (const float*)d_in[1];
    const float* W1 = (const float*)d_in[2];
    const float* b1 = (const float*)d_in[3];
    const float* W2 = (const float*)d_in[4];
    const float* b2 = (const float*)d_in[5];
    const float* W3 = (const float*)d_in[6];
    const float* b3 = (const float*)d_in[7];
    float* out = (float*)d_out;

    compute_E_kernel<<<dim3(16, 16), 256>>>(W1, W2, W3);

    const int smem_bytes =
        (65 * 32 + 512 * H1P + 256 * STP + 32) * (int)sizeof(float);
    cudaFuncSetAttribute(cnf_main_kernel,
                         cudaFuncAttributeMaxDynamicSharedMemorySize, smem_bytes);
    cnf_main_kernel<<<8192 / MT, 256, smem_bytes>>>(t, x, W1, b1, W2, b2,
                                                    W3, b3, out);
}

// round 13
// speedup vs baseline: 1.0125x; 1.0125x over previous
#include <cuda_runtime.h>
#include <math.h>

// CNF_9663676416569: vector field + exact divergence via weight-precomputed E.
//
// dx  = tanh(tanh([t,x] @ W1 + b1) @ W2 + b2) @ W3 + b3
// div = sum_j (1-h2_j^2) * sum_m (1-h1_m^2) * E[m,j]
//   where E[m,j] = W2[m,j] * sum_k W1[1+k, m] * W3[j, k]   (weights only)
//
// R12 (= R11 resubmit after infra failure): B-operands (W2, E) staged in
//      SMEM k-tiles (KT=16) and read via broadcast LDS.128 (free dedup)
//      instead of redundant LDG.128; register prefetch of the next tile
//      hides L2 latency. Keeps R8's A-dup SMEM layout + col-packed FFMA2 +
//      DX replica split.

#define Hm 512
#define Dm 64
#define MT 32
#define H1P 68          // dup'd h1 pitch: 64 dup floats + 4
#define STP 36          // s_st pitch: 32 rows + 4
#define KT  16          // k-tile staged in SMEM

typedef unsigned long long ull;

#define SGN2  0x8000000080000000ULL
#define ONES2 0x3F8000003F800000ULL

__device__ float g_E[Hm * Hm];                  // f32, non-dup
__device__ __align__(16) ull g_W1d[65 * Hm];    // (w,w) pairs for Phase A
__device__ __align__(16) ull g_W3d[Hm * Dm];    // (w,w) pairs for DX

__device__ __forceinline__ ull pack2(float lo, float hi) {
    ull d; asm("mov.b64 %0, {%1, %2};" : "=l"(d) : "f"(lo), "f"(hi)); return d;
}
__device__ __forceinline__ void unpack2(ull v, float& lo, float& hi) {
    asm("mov.b64 {%0, %1}, %2;" : "=f"(lo), "=f"(hi) : "l"(v));
}
__device__ __forceinline__ void ffma2(ull& d, ull a, ull b) {
    asm("fma.rn.f32x2 %0, %1, %2, %0;" : "+l"(d) : "l"(a), "l"(b));
}
__device__ __forceinline__ ull ffma2o(ull a, ull b, ull c) {
    ull d;
    asm("fma.rn.f32x2 %0, %1, %2, %3;" : "=l"(d) : "l"(a), "l"(b), "l"(c));
    return d;
}
__device__ __forceinline__ void fadd2(ull& d, ull a) {
    asm("add.rn.f32x2 %0, %0, %1;" : "+l"(d) : "l"(a));
}

// ---------------------------------------------------------------------------
// Precompute: E = W2 .* (W1[1:,:]^T @ W3^T)  (f32);  dup W1 and W3.
// ---------------------------------------------------------------------------
__global__ __launch_bounds__(256)
void compute_E_kernel(const float* __restrict__ W1,
                      const float* __restrict__ W2,
                      const float* __restrict__ W3) {
    __shared__ float As[64][33];
    __shared__ float Bs[32][65];
    const int m0 = blockIdx.x * 32;
    const int j0 = blockIdx.y * 32;
    const int tid = threadIdx.x;

    for (int p = tid; p < 64 * 32; p += 256) {
        int i = p >> 5, ml = p & 31;
        As[i][ml] = W1[(1 + i) * Hm + m0 + ml];
    }
    for (int p = tid; p < 32 * 64; p += 256) {
        int i = p & 63, jl = p >> 6;
        Bs[jl][i] = W3[(j0 + jl) * 64 + i];
    }
    __syncthreads();

    const int jl = tid & 31;
    const int mg = tid >> 5;
    float acc[4] = {0.f, 0.f, 0.f, 0.f};
    #pragma unroll
    for (int i = 0; i < 64; i++) {
        float b = Bs[jl][i];
        #pragma unroll
        for (int q = 0; q < 4; q++)
            acc[q] = fmaf(As[i][mg * 4 + q], b, acc[q]);
    }
    #pragma unroll
    for (int q = 0; q < 4; q++) {
        int m = m0 + mg * 4 + q;
        int j = j0 + jl;
        g_E[m * Hm + j] = W2[m * Hm + j] * acc[q];
    }

    if (blockIdx.y == 0) {          // dup W1 columns m0..m0+31
        for (int p = tid; p < 65 * 32; p += 256) {
            int c = p >> 5, ml = p & 31;
            const float w = W1[c * Hm + m0 + ml];
            g_W1d[c * Hm + m0 + ml] = pack2(w, w);
        }
    } else if (blockIdx.y == 1) {   // dup W3 rows m0..m0+31
        for (int p = tid; p < 32 * 64; p += 256) {
            int r = p >> 6, cc = p & 63;
            const float w = W3[(m0 + r) * Dm + cc];
            g_W3d[(m0 + r) * Dm + cc] = pack2(w, w);
        }
    }
}

// ---------------------------------------------------------------------------
// Main kernel: one CTA = 32 batch rows, 256 threads, 1 CTA/SM.
// Phase B thread map: rp = tid&7 (rows 4*rp..+3), cg = tid>>3 (cols 8*cg..+7
// within a 256-col chunk; 2 chunks).
// SMEM: s_xaT[65][32], s_h1d[512][68] (dup'd), s_st[256][36],
//       s_w2[KT][256], s_e[KT][256], s_div[32]   (~217 KB)
// ---------------------------------------------------------------------------
__global__ __launch_bounds__(256, 1)
void cnf_main_kernel(const float* __restrict__ t,
                     const float* __restrict__ x,
                     const float* __restrict__ W1,
                     const float* __restrict__ b1,
                     const float* __restrict__ W2,
                     const float* __restrict__ b2,
                     const float* __restrict__ W3,
                     const float* __restrict__ b3,
                     float* __restrict__ out) {
    extern __shared__ float sm[];
    float* s_xaT = sm;                        // 65*32  = 2080
    float* s_h1d = sm + 65 * 32;              // 512*68 = 34816
    float* s_st  = s_h1d + 512 * H1P;         // 256*36 = 9216
    float* s_w2  = s_st + 256 * STP;          // 16*256 = 4096
    float* s_e   = s_w2 + KT * 256;           // 16*256 = 4096
    float* s_div = s_e + KT * 256;            // 32

    const int tid  = threadIdx.x;
    const int row0 = blockIdx.x * MT;

    if (tid < MT) s_div[tid] = 0.f;

    // ---- load [t, x] tile transposed ----
    const float tval = t[0];
    for (int p = tid; p < 65 * 32; p += 256) {
        int c = p >> 5, r = p & 31;
        s_xaT[c * 32 + r] = (c == 0) ? tval
                                     : x[(size_t)(row0 + r) * 65 + (c - 1)];
    }
    __syncthreads();

    // ---- Phase A: H1 = tanh(Xa @ W1 + b1); 2 n per thread; DUP writes ----
    #pragma unroll
    for (int q = 0; q < 2; q++) {
        const int n = tid + q * 256;
        const float bb = b1[n];
        const ull pb = pack2(bb, bb);
        ull acc2[16];
        #pragma unroll
        for (int p = 0; p < 16; p++) acc2[p] = pb;
        #pragma unroll 4
        for (int c = 0; c < 65; c++) {
            const ull pw = g_W1d[c * Hm + n];
            const ull* xa = (const ull*)(s_xaT + c * 32);
            #pragma unroll
            for (int p = 0; p < 16; p++) ffma2(acc2[p], xa[p], pw);
        }
        float* dst = s_h1d + n * H1P;
        #pragma unroll
        for (int p = 0; p < 16; p++) {
            float lo, hi; unpack2(acc2[p], lo, hi);
            const float tl = tanhf(lo), th = tanhf(hi);
            *(float4*)(dst + 4 * p) = make_float4(tl, tl, th, th);
        }
    }
    __syncthreads();

    // ---- Phase B ----
    const int rp = tid & 7;
    const int cg = tid >> 3;          // 0..31
    const int r0 = rp * 4;            // 4 rows
    const int d0 = cg * 8;            // 8 chunk-local cols

    const int cgm = cg & 15;          // DX col group (two kk-half replicas)
    const int d3  = cgm * 4;          // 4 dx cols
    const int kk0 = (cg >> 4) * 128;  // DX kk half

    // staging map: 4 float4 per array per thread
    const int sg_k  = tid >> 6;              // 0..3 (row group base)
    const int sg_c  = (tid & 63) * 4;        // col within row

    ull accDX[2][4];
    #pragma unroll
    for (int h = 0; h < 2; h++)
        #pragma unroll
        for (int j = 0; j < 4; j++) accDX[h][j] = 0ull;
    float divacc[4] = {0.f, 0.f, 0.f, 0.f};

    for (int ch = 0; ch < 2; ch++) {
        const int n0 = ch * 256;

        // init accZ with b2 pairs
        const float4* pb2p = (const float4*)(b2 + n0 + d0);
        const ulonglong2 bA = *(const ulonglong2*)(pb2p);
        const ulonglong2 bB = *(const ulonglong2*)(pb2p + 1);
        ull accZ[4][4], accU[4][4];
        #pragma unroll
        for (int i = 0; i < 4; i++) {
            accZ[i][0] = bA.x; accZ[i][1] = bA.y;
            accZ[i][2] = bB.x; accZ[i][3] = bB.y;
            accU[i][0] = 0ull; accU[i][1] = 0ull;
            accU[i][2] = 0ull; accU[i][3] = 0ull;
        }

        const float* __restrict__ srcW = W2  + n0 + sg_c;
        const float* __restrict__ srcE = g_E + n0 + sg_c;

        // preload tile 0 into registers
        float4 pw[4], pe[4];
        #pragma unroll
        for (int q = 0; q < 4; q++) {
            const int kr = sg_k + q * 4;
            pw[q] = *(const float4*)(srcW + (size_t)kr * Hm);
            pe[q] = *(const float4*)(srcE + (size_t)kr * Hm);
        }

        const float* __restrict__ ph = s_h1d + 8 * rp;

        for (int kt = 0; kt < Hm / KT; kt++) {
            __syncthreads();       // previous tile's readers done
            #pragma unroll
            for (int q = 0; q < 4; q++) {
                const int kr = sg_k + q * 4;
                *(float4*)(s_w2 + kr * 256 + sg_c) = pw[q];
                *(float4*)(s_e  + kr * 256 + sg_c) = pe[q];
            }
            __syncthreads();

            // prefetch next tile (clamped address on last iter -> no branch)
            {
                const int ktn = (kt + 1 < Hm / KT) ? (kt + 1) : kt;
                const int k0n = ktn * KT;
                #pragma unroll
                for (int q = 0; q < 4; q++) {
                    const int kr = k0n + sg_k + q * 4;
                    pw[q] = *(const float4*)(srcW + (size_t)kr * Hm);
                    pe[q] = *(const float4*)(srcE + (size_t)kr * Hm);
                }
            }

            const int k0 = kt * KT;
            #pragma unroll 4
            for (int kk = 0; kk < KT; kk++) {
                const int k = k0 + kk;
                // A: dup'd pairs, rows 4rp..4rp+3 (SMEM)
                const ulonglong2 a01 = *(const ulonglong2*)(ph + k * H1P);
                const ulonglong2 a23 = *(const ulonglong2*)(ph + k * H1P + 4);
                const ull av[4] = {a01.x, a01.y, a23.x, a23.y};
                ull gv[4];
                #pragma unroll
                for (int i = 0; i < 4; i++)
                    gv[i] = ffma2o(av[i], av[i] ^ SGN2, ONES2);

                // B: broadcast LDS.128 of staged tiles
                const ulonglong2 wA = *(const ulonglong2*)(s_w2 + kk * 256 + d0);
                const ulonglong2 wB = *(const ulonglong2*)(s_w2 + kk * 256 + d0 + 4);
                const ulonglong2 eA = *(const ulonglong2*)(s_e  + kk * 256 + d0);
                const ulonglong2 eB = *(const ulonglong2*)(s_e  + kk * 256 + d0 + 4);

                #pragma unroll
                for (int i = 0; i < 4; i++) {
                    ffma2(accZ[i][0], av[i], wA.x);
                    ffma2(accZ[i][1], av[i], wA.y);
                    ffma2(accZ[i][2], av[i], wB.x);
                    ffma2(accZ[i][3], av[i], wB.y);
                    ffma2(accU[i][0], gv[i], eA.x);
                    ffma2(accU[i][1], gv[i], eA.y);
                    ffma2(accU[i][2], gv[i], eB.x);
                    ffma2(accU[i][3], gv[i], eB.y);
                }
            }
        }

        // h2 / g2 / div partials; stage h2 transposed [col][row]
        float h2v[8][4];                 // [chunk-local col j][row i]
        #pragma unroll
        for (int i = 0; i < 4; i++) {
            float dvi = 0.f;
            #pragma unroll
            for (int jp = 0; jp < 4; jp++) {
                float zl, zh, ul, uh;
                unpack2(accZ[i][jp], zl, zh);
                unpack2(accU[i][jp], ul, uh);
                const float hl = tanhf(zl), hh = tanhf(zh);
                dvi = fmaf(fmaf(-hl, hl, 1.f), ul, dvi);
                dvi = fmaf(fmaf(-hh, hh, 1.f), uh, dvi);
                h2v[2 * jp][i]     = hl;
                h2v[2 * jp + 1][i] = hh;
            }
            divacc[i] += dvi;
        }
        __syncthreads();   // protect s_st from previous DX read
        #pragma unroll
        for (int j = 0; j < 8; j++)
            *(float4*)(s_st + (d0 + j) * STP + r0) =
                make_float4(h2v[j][0], h2v[j][1], h2v[j][2], h2v[j][3]);
        __syncthreads();

        // accDX += h2_chunk[:, kk0:kk0+128] @ W3[n0+kk0 : n0+kk0+128, d3:d3+4]
        const ulonglong2* __restrict__ pW3 =
            (const ulonglong2*)g_W3d + (d3 >> 1);
        #pragma unroll 8
        for (int kk = 0; kk < 128; kk++) {
            const int kc = kk0 + kk;
            const ulonglong2 a = *(const ulonglong2*)(s_st + kc * STP + r0);
            const ulonglong2 w0 = pW3[(size_t)(n0 + kc) * 32];
            const ulonglong2 w1 = pW3[(size_t)(n0 + kc) * 32 + 1];
            ffma2(accDX[0][0], a.x, w0.x); ffma2(accDX[0][1], a.x, w0.y);
            ffma2(accDX[0][2], a.x, w1.x); ffma2(accDX[0][3], a.x, w1.y);
            ffma2(accDX[1][0], a.y, w0.x); ffma2(accDX[1][1], a.y, w0.y);
            ffma2(accDX[1][2], a.y, w1.x); ffma2(accDX[1][3], a.y, w1.y);
        }
        __syncthreads();
    }

    // ---- DX replica reduction (cg>=16 half adds into cg<16 half) ----
    ull* s_red = (ull*)s_st;
    if (cg >= 16) {
        ull* dst = s_red + ((size_t)(cgm * 8 + rp)) * 8;
        #pragma unroll
        for (int h = 0; h < 2; h++)
            #pragma unroll
            for (int j = 0; j < 4; j++) dst[h * 4 + j] = accDX[h][j];
    }
    __syncthreads();
    if (cg < 16) {
        const ull* src = s_red + ((size_t)(cgm * 8 + rp)) * 8;
        #pragma unroll
        for (int h = 0; h < 2; h++)
            #pragma unroll
            for (int j = 0; j < 4; j++) fadd2(accDX[h][j], src[h * 4 + j]);
    }

    // ---- epilogue ----
    #pragma unroll
    for (int i = 0; i < 4; i++) atomicAdd(&s_div[r0 + i], divacc[i]);

    if (cg < 16) {
        const float4 b3v = *(const float4*)(b3 + d3);
        #pragma unroll
        for (int h = 0; h < 2; h++) {
            float v[2][4];
            #pragma unroll
            for (int j = 0; j < 4; j++) unpack2(accDX[h][j], v[0][j], v[1][j]);
            #pragma unroll
            for (int s = 0; s < 2; s++) {
                const size_t ro = (size_t)(row0 + r0 + 2 * h + s) * 65 + d3;
                out[ro + 0] = v[s][0] + b3v.x;
                out[ro + 1] = v[s][1] + b3v.y;
                out[ro + 2] = v[s][2] + b3v.z;
                out[ro + 3] = v[s][3] + b3v.w;
            }
        }
    }
    __syncthreads();
    if (tid < MT)
        out[(size_t)(row0 + tid) * 65 + 64] = s_div[tid];
}

// ---------------------------------------------------------------------------
extern "C" void kernel_launch(void* const* d_in, const int* in_sizes, int n_in,
                              void* d_out, int out_size) {
    const float* t  = (const float*)d_in[0];
    const float* x  = (const float*)d_in[1];
    const float* W1 = (const float*)d_in[2];
    const float* b1 = (const float*)d_in[3];
    const float* W2 = (const float*)d_in[4];
    const float* b2 = (const float*)d_in[5];
    const float* W3 = (const float*)d_in[6];
    const float* b3 = (const float*)d_in[7];
    float* out = (float*)d_out;

    compute_E_kernel<<<dim3(16, 16), 256>>>(W1, W2, W3);

    const int smem_bytes =
        (65 * 32 + 512 * H1P + 256 * STP + 2 * KT * 256 + 32) *
        (int)sizeof(float);
    cudaFuncSetAttribute(cnf_main_kernel,
                         cudaFuncAttributeMaxDynamicSharedMemorySize, smem_bytes);
    cnf_main_kernel<<<8192 / MT, 256, smem_bytes>>>(t, x, W1, b1, W2, b2,
                                                    W3, b3, out);
}